// round 1
// baseline (speedup 1.0000x reference)
#include <cuda_runtime.h>
#include <cuda_bf16.h>
#include <cstddef>

// Problem constants
#define BATCH 4
#define SEQ   2048
#define CH    1024

// Tiling
#define BM 128
#define BN 128
#define BK 16
#define TM 8
#define TN 8
#define NTHREADS 256

// Scratch (device globals — no runtime allocation allowed)
__device__ float g_Q[(size_t)BATCH * SEQ * CH];
__device__ float g_K[(size_t)BATCH * SEQ * CH];
__device__ float g_V[(size_t)BATCH * SEQ * CH];
__device__ float g_S[(size_t)BATCH * SEQ * SEQ];

// ---------------------------------------------------------------------------
// NT GEMM: C[m,n] = alpha * sum_k A[m,k] * B[n,k]  (+ bias[n] if given)
// A: [M,K] row-major, B: [N,K] row-major. All dims divisible by tiles.
// ---------------------------------------------------------------------------
__global__ void __launch_bounds__(NTHREADS)
gemm_nt_kernel(const float* __restrict__ Ag, const float* __restrict__ Bg,
               float* __restrict__ Cg, const float* __restrict__ bias,
               int M, int N, int K, float alpha,
               size_t sA, size_t sB, size_t sC)
{
    const int bz = blockIdx.z;
    const float* A = Ag + (size_t)bz * sA;
    const float* B = Bg + (size_t)bz * sB;
    float* C = Cg + (size_t)bz * sC;

    __shared__ float As[BK][BM];
    __shared__ float Bs[BK][BN];

    const int tid = threadIdx.x;
    const int tx = tid & 15;     // 0..15
    const int ty = tid >> 4;     // 0..15
    const int m0 = blockIdx.y * BM;
    const int n0 = blockIdx.x * BN;

    float acc[TM][TN];
#pragma unroll
    for (int i = 0; i < TM; i++)
#pragma unroll
        for (int j = 0; j < TN; j++) acc[i][j] = 0.0f;

    for (int k0 = 0; k0 < K; k0 += BK) {
        // Load A tile: BM rows x BK k (k-contiguous) -> As[k][m]
#pragma unroll
        for (int it = 0; it < 2; it++) {
            int idx = tid + it * NTHREADS;         // 0..511
            int row = idx >> 2;                    // 0..127
            int kq  = (idx & 3) * 4;               // 0,4,8,12
            float4 v = *reinterpret_cast<const float4*>(
                &A[(size_t)(m0 + row) * K + k0 + kq]);
            As[kq + 0][row] = v.x;
            As[kq + 1][row] = v.y;
            As[kq + 2][row] = v.z;
            As[kq + 3][row] = v.w;
        }
        // Load B tile: BN rows x BK k -> Bs[k][n]
#pragma unroll
        for (int it = 0; it < 2; it++) {
            int idx = tid + it * NTHREADS;
            int row = idx >> 2;
            int kq  = (idx & 3) * 4;
            float4 v = *reinterpret_cast<const float4*>(
                &B[(size_t)(n0 + row) * K + k0 + kq]);
            Bs[kq + 0][row] = v.x;
            Bs[kq + 1][row] = v.y;
            Bs[kq + 2][row] = v.z;
            Bs[kq + 3][row] = v.w;
        }
        __syncthreads();

#pragma unroll
        for (int kk = 0; kk < BK; kk++) {
            float a[TM], b[TN];
#pragma unroll
            for (int i = 0; i < TM; i++) a[i] = As[kk][ty * TM + i];
#pragma unroll
            for (int j = 0; j < TN; j++) b[j] = Bs[kk][tx * TN + j];
#pragma unroll
            for (int i = 0; i < TM; i++)
#pragma unroll
                for (int j = 0; j < TN; j++)
                    acc[i][j] = fmaf(a[i], b[j], acc[i][j]);
        }
        __syncthreads();
    }

#pragma unroll
    for (int i = 0; i < TM; i++) {
        int m = m0 + ty * TM + i;
#pragma unroll
        for (int j = 0; j < TN; j += 4) {
            int n = n0 + tx * TN + j;
            float4 v;
            v.x = acc[i][j + 0] * alpha;
            v.y = acc[i][j + 1] * alpha;
            v.z = acc[i][j + 2] * alpha;
            v.w = acc[i][j + 3] * alpha;
            if (bias) {
                v.x += bias[n + 0];
                v.y += bias[n + 1];
                v.z += bias[n + 2];
                v.w += bias[n + 3];
            }
            *reinterpret_cast<float4*>(&C[(size_t)m * N + n]) = v;
        }
    }
}

// ---------------------------------------------------------------------------
// NN GEMM: C[m,n] = sum_k A[m,k] * B[k,n]
// A: [M,K] row-major, B: [K,N] row-major.
// ---------------------------------------------------------------------------
__global__ void __launch_bounds__(NTHREADS)
gemm_nn_kernel(const float* __restrict__ Ag, const float* __restrict__ Bg,
               float* __restrict__ Cg,
               int M, int N, int K,
               size_t sA, size_t sB, size_t sC)
{
    const int bz = blockIdx.z;
    const float* A = Ag + (size_t)bz * sA;
    const float* B = Bg + (size_t)bz * sB;
    float* C = Cg + (size_t)bz * sC;

    __shared__ float As[BK][BM];
    __shared__ float Bs[BK][BN];

    const int tid = threadIdx.x;
    const int tx = tid & 15;
    const int ty = tid >> 4;
    const int m0 = blockIdx.y * BM;
    const int n0 = blockIdx.x * BN;

    float acc[TM][TN];
#pragma unroll
    for (int i = 0; i < TM; i++)
#pragma unroll
        for (int j = 0; j < TN; j++) acc[i][j] = 0.0f;

    for (int k0 = 0; k0 < K; k0 += BK) {
        // Load A tile (k-contiguous) -> As[k][m]
#pragma unroll
        for (int it = 0; it < 2; it++) {
            int idx = tid + it * NTHREADS;
            int row = idx >> 2;
            int kq  = (idx & 3) * 4;
            float4 v = *reinterpret_cast<const float4*>(
                &A[(size_t)(m0 + row) * K + k0 + kq]);
            As[kq + 0][row] = v.x;
            As[kq + 1][row] = v.y;
            As[kq + 2][row] = v.z;
            As[kq + 3][row] = v.w;
        }
        // Load B tile: BK rows x BN cols (n-contiguous) -> Bs[k][n] direct
#pragma unroll
        for (int it = 0; it < 2; it++) {
            int idx = tid + it * NTHREADS;         // 0..511
            int row = idx >> 5;                    // 0..15 (BK)
            int c4  = (idx & 31) * 4;              // 0..124
            float4 v = *reinterpret_cast<const float4*>(
                &B[(size_t)(k0 + row) * N + n0 + c4]);
            *reinterpret_cast<float4*>(&Bs[row][c4]) = v;
        }
        __syncthreads();

#pragma unroll
        for (int kk = 0; kk < BK; kk++) {
            float a[TM], b[TN];
#pragma unroll
            for (int i = 0; i < TM; i++) a[i] = As[kk][ty * TM + i];
#pragma unroll
            for (int j = 0; j < TN; j++) b[j] = Bs[kk][tx * TN + j];
#pragma unroll
            for (int i = 0; i < TM; i++)
#pragma unroll
                for (int j = 0; j < TN; j++)
                    acc[i][j] = fmaf(a[i], b[j], acc[i][j]);
        }
        __syncthreads();
    }

#pragma unroll
    for (int i = 0; i < TM; i++) {
        int m = m0 + ty * TM + i;
#pragma unroll
        for (int j = 0; j < TN; j += 4) {
            int n = n0 + tx * TN + j;
            float4 v;
            v.x = acc[i][j + 0];
            v.y = acc[i][j + 1];
            v.z = acc[i][j + 2];
            v.w = acc[i][j + 3];
            *reinterpret_cast<float4*>(&C[(size_t)m * N + n]) = v;
        }
    }
}

// ---------------------------------------------------------------------------
// Row softmax over ncols (ncols divisible by blockDim)
// ---------------------------------------------------------------------------
__global__ void __launch_bounds__(256)
softmax_rows_kernel(float* __restrict__ S, int ncols)
{
    float* row = S + (size_t)blockIdx.x * ncols;
    const int tid = threadIdx.x;
    __shared__ float red[256];

    // max
    float m = -3.402823466e38f;
    for (int c = tid; c < ncols; c += 256) m = fmaxf(m, row[c]);
    red[tid] = m;
    __syncthreads();
#pragma unroll
    for (int s = 128; s > 0; s >>= 1) {
        if (tid < s) red[tid] = fmaxf(red[tid], red[tid + s]);
        __syncthreads();
    }
    m = red[0];
    __syncthreads();

    // exp + sum
    float sum = 0.0f;
    for (int c = tid; c < ncols; c += 256) {
        float e = expf(row[c] - m);
        row[c] = e;
        sum += e;
    }
    red[tid] = sum;
    __syncthreads();
#pragma unroll
    for (int s = 128; s > 0; s >>= 1) {
        if (tid < s) red[tid] += red[tid + s];
        __syncthreads();
    }
    float inv = 1.0f / red[0];
    __syncthreads();

    for (int c = tid; c < ncols; c += 256) row[c] *= inv;
}

// ---------------------------------------------------------------------------
extern "C" void kernel_launch(void* const* d_in, const int* in_sizes, int n_in,
                              void* d_out, int out_size)
{
    const float* query = (const float*)d_in[0];
    const float* key   = (const float*)d_in[1];
    const float* value = (const float*)d_in[2];
    const float* Wq    = (const float*)d_in[3];
    const float* bq    = (const float*)d_in[4];
    const float* Wk    = (const float*)d_in[5];
    const float* bk    = (const float*)d_in[6];
    const float* Wv    = (const float*)d_in[7];
    const float* bv    = (const float*)d_in[8];
    float* out = (float*)d_out;

    float *Q, *K, *V, *S;
    cudaGetSymbolAddress((void**)&Q, g_Q);
    cudaGetSymbolAddress((void**)&K, g_K);
    cudaGetSymbolAddress((void**)&V, g_V);
    cudaGetSymbolAddress((void**)&S, g_S);

    const int M = BATCH * SEQ;           // 8192
    dim3 blk(NTHREADS);

    // Projections: [8192,1024] x [1024,1024]^T + b
    dim3 gp(CH / BN, M / BM, 1);         // (8, 64)
    gemm_nt_kernel<<<gp, blk>>>(query, Wq, Q, bq, M, CH, CH, 1.0f, 0, 0, 0);
    gemm_nt_kernel<<<gp, blk>>>(key,   Wk, K, bk, M, CH, CH, 1.0f, 0, 0, 0);
    gemm_nt_kernel<<<gp, blk>>>(value, Wv, V, bv, M, CH, CH, 1.0f, 0, 0, 0);

    // Scores: per batch, [2048,1024] x [2048,1024]^T * (1/32)
    const size_t qkvStride = (size_t)SEQ * CH;       // 2097152
    const size_t sStride   = (size_t)SEQ * SEQ;      // 4194304
    dim3 gs(SEQ / BN, SEQ / BM, BATCH);  // (16, 16, 4)
    gemm_nt_kernel<<<gs, blk>>>(Q, K, S, nullptr, SEQ, SEQ, CH,
                                1.0f / 32.0f, qkvStride, qkvStride, sStride);

    // Softmax over last dim
    softmax_rows_kernel<<<BATCH * SEQ, 256>>>(S, SEQ);

    // Out: per batch, [2048,2048] x [2048,1024]
    dim3 go(CH / BN, SEQ / BM, BATCH);   // (8, 16, 4)
    gemm_nn_kernel<<<go, blk>>>(S, V, out, SEQ, CH, SEQ,
                                sStride, qkvStride, qkvStride);
}

// round 2
// speedup vs baseline: 1.0529x; 1.0529x over previous
#include <cuda_runtime.h>
#include <cuda_bf16.h>
#include <cstddef>

// Problem constants
#define BATCH 4
#define SEQ   2048
#define CH    1024

// Tiling
#define BM 128
#define BN 128
#define BK 16
#define TM 8
#define TN 8
#define NTHREADS 256

// Scratch (device globals — no runtime allocation allowed)
__device__ float g_Q[(size_t)BATCH * SEQ * CH];
__device__ float g_K[(size_t)BATCH * SEQ * CH];
__device__ float g_V[(size_t)BATCH * SEQ * CH];
__device__ float g_S[(size_t)BATCH * SEQ * SEQ];

// ---------------------------------------------------------------------------
// NT GEMM: C[m,n] = alpha * sum_k A[m,k] * B[n,k]  (+ bias[n] if given)
// A: [M,K] row-major, B: [N,K] row-major. All dims divisible by tiles.
// ---------------------------------------------------------------------------
__global__ void __launch_bounds__(NTHREADS)
gemm_nt_kernel(const float* __restrict__ Ag, const float* __restrict__ Bg,
               float* __restrict__ Cg, const float* __restrict__ bias,
               int M, int N, int K, float alpha,
               size_t sA, size_t sB, size_t sC)
{
    const int bz = blockIdx.z;
    const float* A = Ag + (size_t)bz * sA;
    const float* B = Bg + (size_t)bz * sB;
    float* C = Cg + (size_t)bz * sC;

    __shared__ float As[BK][BM];
    __shared__ float Bs[BK][BN];

    const int tid = threadIdx.x;
    const int tx = tid & 15;     // 0..15
    const int ty = tid >> 4;     // 0..15
    const int m0 = blockIdx.y * BM;
    const int n0 = blockIdx.x * BN;

    float acc[TM][TN];
#pragma unroll
    for (int i = 0; i < TM; i++)
#pragma unroll
        for (int j = 0; j < TN; j++) acc[i][j] = 0.0f;

    for (int k0 = 0; k0 < K; k0 += BK) {
        // Load A tile: BM rows x BK k (k-contiguous) -> As[k][m]
#pragma unroll
        for (int it = 0; it < 2; it++) {
            int idx = tid + it * NTHREADS;         // 0..511
            int row = idx >> 2;                    // 0..127
            int kq  = (idx & 3) * 4;               // 0,4,8,12
            float4 v = *reinterpret_cast<const float4*>(
                &A[(size_t)(m0 + row) * K + k0 + kq]);
            As[kq + 0][row] = v.x;
            As[kq + 1][row] = v.y;
            As[kq + 2][row] = v.z;
            As[kq + 3][row] = v.w;
        }
        // Load B tile: BN rows x BK k -> Bs[k][n]
#pragma unroll
        for (int it = 0; it < 2; it++) {
            int idx = tid + it * NTHREADS;
            int row = idx >> 2;
            int kq  = (idx & 3) * 4;
            float4 v = *reinterpret_cast<const float4*>(
                &B[(size_t)(n0 + row) * K + k0 + kq]);
            Bs[kq + 0][row] = v.x;
            Bs[kq + 1][row] = v.y;
            Bs[kq + 2][row] = v.z;
            Bs[kq + 3][row] = v.w;
        }
        __syncthreads();

#pragma unroll
        for (int kk = 0; kk < BK; kk++) {
            float a[TM], b[TN];
#pragma unroll
            for (int i = 0; i < TM; i++) a[i] = As[kk][ty * TM + i];
#pragma unroll
            for (int j = 0; j < TN; j++) b[j] = Bs[kk][tx * TN + j];
#pragma unroll
            for (int i = 0; i < TM; i++)
#pragma unroll
                for (int j = 0; j < TN; j++)
                    acc[i][j] = fmaf(a[i], b[j], acc[i][j]);
        }
        __syncthreads();
    }

#pragma unroll
    for (int i = 0; i < TM; i++) {
        int m = m0 + ty * TM + i;
#pragma unroll
        for (int j = 0; j < TN; j += 4) {
            int n = n0 + tx * TN + j;
            float4 v;
            v.x = acc[i][j + 0] * alpha;
            v.y = acc[i][j + 1] * alpha;
            v.z = acc[i][j + 2] * alpha;
            v.w = acc[i][j + 3] * alpha;
            if (bias) {
                v.x += bias[n + 0];
                v.y += bias[n + 1];
                v.z += bias[n + 2];
                v.w += bias[n + 3];
            }
            *reinterpret_cast<float4*>(&C[(size_t)m * N + n]) = v;
        }
    }
}

// ---------------------------------------------------------------------------
// NN GEMM: C[m,n] = sum_k A[m,k] * B[k,n]
// A: [M,K] row-major, B: [K,N] row-major.
// ---------------------------------------------------------------------------
__global__ void __launch_bounds__(NTHREADS)
gemm_nn_kernel(const float* __restrict__ Ag, const float* __restrict__ Bg,
               float* __restrict__ Cg,
               int M, int N, int K,
               size_t sA, size_t sB, size_t sC)
{
    const int bz = blockIdx.z;
    const float* A = Ag + (size_t)bz * sA;
    const float* B = Bg + (size_t)bz * sB;
    float* C = Cg + (size_t)bz * sC;

    __shared__ float As[BK][BM];
    __shared__ float Bs[BK][BN];

    const int tid = threadIdx.x;
    const int tx = tid & 15;
    const int ty = tid >> 4;
    const int m0 = blockIdx.y * BM;
    const int n0 = blockIdx.x * BN;

    float acc[TM][TN];
#pragma unroll
    for (int i = 0; i < TM; i++)
#pragma unroll
        for (int j = 0; j < TN; j++) acc[i][j] = 0.0f;

    for (int k0 = 0; k0 < K; k0 += BK) {
        // Load A tile (k-contiguous) -> As[k][m]
#pragma unroll
        for (int it = 0; it < 2; it++) {
            int idx = tid + it * NTHREADS;
            int row = idx >> 2;
            int kq  = (idx & 3) * 4;
            float4 v = *reinterpret_cast<const float4*>(
                &A[(size_t)(m0 + row) * K + k0 + kq]);
            As[kq + 0][row] = v.x;
            As[kq + 1][row] = v.y;
            As[kq + 2][row] = v.z;
            As[kq + 3][row] = v.w;
        }
        // Load B tile: BK rows x BN cols (n-contiguous) -> Bs[k][n] direct
#pragma unroll
        for (int it = 0; it < 2; it++) {
            int idx = tid + it * NTHREADS;         // 0..511
            int row = idx >> 5;                    // 0..15 (BK)
            int c4  = (idx & 31) * 4;              // 0..124
            float4 v = *reinterpret_cast<const float4*>(
                &B[(size_t)(k0 + row) * N + n0 + c4]);
            *reinterpret_cast<float4*>(&Bs[row][c4]) = v;
        }
        __syncthreads();

#pragma unroll
        for (int kk = 0; kk < BK; kk++) {
            float a[TM], b[TN];
#pragma unroll
            for (int i = 0; i < TM; i++) a[i] = As[kk][ty * TM + i];
#pragma unroll
            for (int j = 0; j < TN; j++) b[j] = Bs[kk][tx * TN + j];
#pragma unroll
            for (int i = 0; i < TM; i++)
#pragma unroll
                for (int j = 0; j < TN; j++)
                    acc[i][j] = fmaf(a[i], b[j], acc[i][j]);
        }
        __syncthreads();
    }

#pragma unroll
    for (int i = 0; i < TM; i++) {
        int m = m0 + ty * TM + i;
#pragma unroll
        for (int j = 0; j < TN; j += 4) {
            int n = n0 + tx * TN + j;
            float4 v;
            v.x = acc[i][j + 0];
            v.y = acc[i][j + 1];
            v.z = acc[i][j + 2];
            v.w = acc[i][j + 3];
            *reinterpret_cast<float4*>(&C[(size_t)m * N + n]) = v;
        }
    }
}

// ---------------------------------------------------------------------------
// Row softmax over ncols (ncols divisible by blockDim)
// ---------------------------------------------------------------------------
__global__ void __launch_bounds__(256)
softmax_rows_kernel(float* __restrict__ S, int ncols)
{
    float* row = S + (size_t)blockIdx.x * ncols;
    const int tid = threadIdx.x;
    __shared__ float red[256];

    // max
    float m = -3.402823466e38f;
    for (int c = tid; c < ncols; c += 256) m = fmaxf(m, row[c]);
    red[tid] = m;
    __syncthreads();
#pragma unroll
    for (int s = 128; s > 0; s >>= 1) {
        if (tid < s) red[tid] = fmaxf(red[tid], red[tid + s]);
        __syncthreads();
    }
    m = red[0];
    __syncthreads();

    // exp + sum
    float sum = 0.0f;
    for (int c = tid; c < ncols; c += 256) {
        float e = expf(row[c] - m);
        row[c] = e;
        sum += e;
    }
    red[tid] = sum;
    __syncthreads();
#pragma unroll
    for (int s = 128; s > 0; s >>= 1) {
        if (tid < s) red[tid] += red[tid + s];
        __syncthreads();
    }
    float inv = 1.0f / red[0];
    __syncthreads();

    for (int c = tid; c < ncols; c += 256) row[c] *= inv;
}

// ---------------------------------------------------------------------------
extern "C" void kernel_launch(void* const* d_in, const int* in_sizes, int n_in,
                              void* d_out, int out_size)
{
    const float* query = (const float*)d_in[0];
    const float* key   = (const float*)d_in[1];
    const float* value = (const float*)d_in[2];
    const float* Wq    = (const float*)d_in[3];
    const float* bq    = (const float*)d_in[4];
    const float* Wk    = (const float*)d_in[5];
    const float* bk    = (const float*)d_in[6];
    const float* Wv    = (const float*)d_in[7];
    const float* bv    = (const float*)d_in[8];
    float* out = (float*)d_out;

    float *Q, *K, *V, *S;
    cudaGetSymbolAddress((void**)&Q, g_Q);
    cudaGetSymbolAddress((void**)&K, g_K);
    cudaGetSymbolAddress((void**)&V, g_V);
    cudaGetSymbolAddress((void**)&S, g_S);

    const int M = BATCH * SEQ;           // 8192
    dim3 blk(NTHREADS);

    // Projections: [8192,1024] x [1024,1024]^T + b
    dim3 gp(CH / BN, M / BM, 1);         // (8, 64)
    gemm_nt_kernel<<<gp, blk>>>(query, Wq, Q, bq, M, CH, CH, 1.0f, 0, 0, 0);
    gemm_nt_kernel<<<gp, blk>>>(key,   Wk, K, bk, M, CH, CH, 1.0f, 0, 0, 0);
    gemm_nt_kernel<<<gp, blk>>>(value, Wv, V, bv, M, CH, CH, 1.0f, 0, 0, 0);

    // Scores: per batch, [2048,1024] x [2048,1024]^T * (1/32)
    const size_t qkvStride = (size_t)SEQ * CH;       // 2097152
    const size_t sStride   = (size_t)SEQ * SEQ;      // 4194304
    dim3 gs(SEQ / BN, SEQ / BM, BATCH);  // (16, 16, 4)
    gemm_nt_kernel<<<gs, blk>>>(Q, K, S, nullptr, SEQ, SEQ, CH,
                                1.0f / 32.0f, qkvStride, qkvStride, sStride);

    // Softmax over last dim
    softmax_rows_kernel<<<BATCH * SEQ, 256>>>(S, SEQ);

    // Out: per batch, [2048,2048] x [2048,1024]
    dim3 go(CH / BN, SEQ / BM, BATCH);   // (8, 16, 4)
    gemm_nn_kernel<<<go, blk>>>(S, V, out, SEQ, CH, SEQ,
                                sStride, qkvStride, qkvStride);
}

// round 4
// speedup vs baseline: 2.2821x; 2.1675x over previous
#include <cuda_runtime.h>
#include <cuda_bf16.h>
#include <mma.h>
#include <cstdint>
#include <cstddef>

using namespace nvcuda;

#define BATCH 4
#define SEQ   2048
#define CH    1024

#define BKC 32                       // k per stage
#define BKP 40                       // padded smem ld (elems)
#define ARR_BYTES (128 * BKP * 2)    // one operand array: 10240 B
#define STAGE_BYTES (4 * ARR_BYTES)  // Ah, Al, Bh, Bl: 40960 B
#define NSTAGE 3
#define GEMM_SMEM (NSTAGE * STAGE_BYTES)   // 122880 B (epilogue reuses 64KB)

// ---------------------------------------------------------------------------
// helpers
// ---------------------------------------------------------------------------
__device__ __forceinline__ uint32_t smem_u32(const void* p) {
    uint32_t a;
    asm("{ .reg .u64 t; cvta.to.shared.u64 t, %1; cvt.u32.u64 %0, t; }"
        : "=r"(a) : "l"(p));
    return a;
}

__device__ __forceinline__ void cp_async16(void* dst, const void* src) {
    uint32_t d = smem_u32(dst);
    asm volatile("cp.async.cg.shared.global [%0], [%1], 16;"
                 :: "r"(d), "l"(src) : "memory");
}
__device__ __forceinline__ void cp_commit() {
    asm volatile("cp.async.commit_group;" ::: "memory");
}
template <int N>
__device__ __forceinline__ void cp_wait_group() {
    asm volatile("cp.async.wait_group %0;" :: "n"(N) : "memory");
}

// fp32 pair -> hi/lo bf16x2 words
__device__ __forceinline__ void split2(float a, float b, uint32_t& hi, uint32_t& lo) {
    __nv_bfloat16 ha = __float2bfloat16(a);
    __nv_bfloat16 hb = __float2bfloat16(b);
    __nv_bfloat16 la = __float2bfloat16(a - __bfloat162float(ha));
    __nv_bfloat16 lb = __float2bfloat16(b - __bfloat162float(hb));
    hi = (uint32_t)__bfloat16_as_ushort(ha) | ((uint32_t)__bfloat16_as_ushort(hb) << 16);
    lo = (uint32_t)__bfloat16_as_ushort(la) | ((uint32_t)__bfloat16_as_ushort(lb) << 16);
}

// ---------------------------------------------------------------------------
// scratch (row-major everywhere)
// ---------------------------------------------------------------------------
#define NXE ((size_t)BATCH * SEQ * CH)      // 8388608
#define NWE ((size_t)CH * CH)
#define NSE ((size_t)BATCH * SEQ * SEQ)

__device__ __align__(1024) __nv_bfloat16 g_xqh[NXE], g_xql[NXE];
__device__ __align__(1024) __nv_bfloat16 g_xkh[NXE], g_xkl[NXE];
__device__ __align__(1024) __nv_bfloat16 g_xvh[NXE], g_xvl[NXE];
__device__ __align__(1024) __nv_bfloat16 g_wqh[NWE], g_wql[NWE];
__device__ __align__(1024) __nv_bfloat16 g_wkh[NWE], g_wkl[NWE];
__device__ __align__(1024) __nv_bfloat16 g_wvh[NWE], g_wvl[NWE];
__device__ __align__(1024) __nv_bfloat16 g_Qh[NXE],  g_Ql[NXE];
__device__ __align__(1024) __nv_bfloat16 g_Kh[NXE],  g_Kl[NXE];
__device__ __align__(1024) float         g_Vf[NXE];
__device__ __align__(1024) __nv_bfloat16 g_Vth[NXE], g_Vtl[NXE];
__device__ __align__(1024) float         g_Sf[NSE];
__device__ __align__(1024) __nv_bfloat16 g_Sh[NSE],  g_Sl[NSE];

// ---------------------------------------------------------------------------
// elementwise fp32 -> hi/lo bf16 (row-major), 8 elems/thread
// ---------------------------------------------------------------------------
__global__ void __launch_bounds__(256)
convert_pack(const float* __restrict__ src,
             __nv_bfloat16* __restrict__ Dh, __nv_bfloat16* __restrict__ Dl)
{
    size_t base = ((size_t)blockIdx.x * 256 + threadIdx.x) * 8;
    float4 f0 = *reinterpret_cast<const float4*>(src + base);
    float4 f1 = *reinterpret_cast<const float4*>(src + base + 4);
    uint4 H, L;
    split2(f0.x, f0.y, H.x, L.x);
    split2(f0.z, f0.w, H.y, L.y);
    split2(f1.x, f1.y, H.z, L.z);
    split2(f1.z, f1.w, H.w, L.w);
    *reinterpret_cast<uint4*>((char*)Dh + base * 2) = H;
    *reinterpret_cast<uint4*>((char*)Dl + base * 2) = L;
}

// ---------------------------------------------------------------------------
// V fp32 [B][S][C] -> V^T hi/lo [B][C][S]
// grid (32 s-chunks of 64, 8 d-chunks of 128, B), 256 thr
// ---------------------------------------------------------------------------
__global__ void __launch_bounds__(256)
transpose_pack(const float* __restrict__ V,
               __nv_bfloat16* __restrict__ Dh, __nv_bfloat16* __restrict__ Dl)
{
    __shared__ float sb[64 * 129];
    int kc = blockIdx.x, dBlk = blockIdx.y, b = blockIdx.z;
    int seq0 = kc * 64, d0 = dBlk * 128;
    int t = threadIdx.x;
#pragma unroll
    for (int i = 0; i < 8; i++) {
        int idx = t + i * 256;                 // 2048 float4 slots
        int s = idx >> 5, d4 = (idx & 31) * 4;
        float4 v = *reinterpret_cast<const float4*>(
            V + ((size_t)b * SEQ + seq0 + s) * CH + d0 + d4);
        sb[s * 129 + d4 + 0] = v.x;
        sb[s * 129 + d4 + 1] = v.y;
        sb[s * 129 + d4 + 2] = v.z;
        sb[s * 129 + d4 + 3] = v.w;
    }
    __syncthreads();
#pragma unroll
    for (int i = 0; i < 4; i++) {
        int idx = t + i * 256;                 // 1024 jobs: 128 d x 8 s-groups
        int d = idx >> 3, s8 = (idx & 7) * 8;
        uint4 H, L;
        float v0 = sb[(s8 + 0) * 129 + d], v1 = sb[(s8 + 1) * 129 + d];
        float v2 = sb[(s8 + 2) * 129 + d], v3 = sb[(s8 + 3) * 129 + d];
        float v4 = sb[(s8 + 4) * 129 + d], v5 = sb[(s8 + 5) * 129 + d];
        float v6 = sb[(s8 + 6) * 129 + d], v7 = sb[(s8 + 7) * 129 + d];
        split2(v0, v1, H.x, L.x);
        split2(v2, v3, H.y, L.y);
        split2(v4, v5, H.z, L.z);
        split2(v6, v7, H.w, L.w);
        size_t e = ((size_t)b * CH + d0 + d) * SEQ + seq0 + s8;
        *reinterpret_cast<uint4*>((char*)Dh + e * 2) = H;
        *reinterpret_cast<uint4*>((char*)Dl + e * 2) = L;
    }
}

// ---------------------------------------------------------------------------
// softmax over rows of S fp32 [B*S][2048] -> hi/lo bf16 row-major
// grid 8192, 256 thr (8 cols/thread)
// ---------------------------------------------------------------------------
__global__ void __launch_bounds__(256)
softmax_pack(const float* __restrict__ S,
             __nv_bfloat16* __restrict__ Dh, __nv_bfloat16* __restrict__ Dl)
{
    __shared__ float red[32];
    int rowG = blockIdx.x, t = threadIdx.x;
    const float* row = S + (size_t)rowG * SEQ;
    float4 a = *reinterpret_cast<const float4*>(row + t * 8);
    float4 b2 = *reinterpret_cast<const float4*>(row + t * 8 + 4);
    float v[8] = {a.x, a.y, a.z, a.w, b2.x, b2.y, b2.z, b2.w};

    float m = v[0];
#pragma unroll
    for (int i = 1; i < 8; i++) m = fmaxf(m, v[i]);
#pragma unroll
    for (int o = 16; o > 0; o >>= 1)
        m = fmaxf(m, __shfl_xor_sync(0xffffffffu, m, o));
    if ((t & 31) == 0) red[t >> 5] = m;
    __syncthreads();
    if (t < 32) {
        float x = (t < 8) ? red[t] : -3.4e38f;
#pragma unroll
        for (int o = 4; o > 0; o >>= 1) x = fmaxf(x, __shfl_xor_sync(0xffffffffu, x, o));
        if (t == 0) red[0] = x;
    }
    __syncthreads();
    m = red[0];
    __syncthreads();

    float sum = 0.0f;
#pragma unroll
    for (int i = 0; i < 8; i++) { v[i] = __expf(v[i] - m); sum += v[i]; }
#pragma unroll
    for (int o = 16; o > 0; o >>= 1) sum += __shfl_xor_sync(0xffffffffu, sum, o);
    if ((t & 31) == 0) red[t >> 5] = sum;
    __syncthreads();
    if (t < 32) {
        float x = (t < 8) ? red[t] : 0.0f;
#pragma unroll
        for (int o = 4; o > 0; o >>= 1) x += __shfl_xor_sync(0xffffffffu, x, o);
        if (t == 0) red[0] = x;
    }
    __syncthreads();
    float inv = 1.0f / red[0];

    uint4 H, L;
    split2(v[0] * inv, v[1] * inv, H.x, L.x);
    split2(v[2] * inv, v[3] * inv, H.y, L.y);
    split2(v[4] * inv, v[5] * inv, H.z, L.z);
    split2(v[6] * inv, v[7] * inv, H.w, L.w);
    size_t e = (size_t)rowG * SEQ + t * 8;
    *reinterpret_cast<uint4*>((char*)Dh + e * 2) = H;
    *reinterpret_cast<uint4*>((char*)Dl + e * 2) = L;
}

// ---------------------------------------------------------------------------
// WMMA bf16 hi/lo-split NT GEMM:
//   C[m,n] = alpha * sum_k A[m,k]*B[n,k] (+ bias[n])
// A,B row-major with ld = K. 128x128 CTA tile, 8 warps (4m x 2n),
// 3-stage cp.async pipeline, BK=32 per stage.
// Outputs: fp32 (outF/ldC/cStride) and/or hi/lo bf16 (outH,outL/ldP/pStride).
// ---------------------------------------------------------------------------
__global__ void __launch_bounds__(256)
tc_gemm(const __nv_bfloat16* __restrict__ Ah, const __nv_bfloat16* __restrict__ Al,
        const __nv_bfloat16* __restrict__ Bh, const __nv_bfloat16* __restrict__ Bl,
        int K, size_t aStride, size_t bStride,
        const float* __restrict__ bias, float alpha,
        float* __restrict__ outF, int ldC, size_t cStride,
        __nv_bfloat16* __restrict__ outH, __nv_bfloat16* __restrict__ outL,
        int ldP, size_t pStride)
{
    extern __shared__ char smem[];
    const int tid = threadIdx.x;
    const int wid = tid >> 5;
    const int bx = blockIdx.x, by = blockIdx.y, bz = blockIdx.z;
    const int m0 = by * 128, n0 = bx * 128;

    const __nv_bfloat16* Ahb = Ah + (size_t)bz * aStride + (size_t)m0 * K;
    const __nv_bfloat16* Alb = Al + (size_t)bz * aStride + (size_t)m0 * K;
    const __nv_bfloat16* Bhb = Bh + (size_t)bz * bStride + (size_t)n0 * K;
    const __nv_bfloat16* Blb = Bl + (size_t)bz * bStride + (size_t)n0 * K;

    const int nK = K / BKC;

    auto load_stage = [&](int s, int c) {
        char* st = smem + s * STAGE_BYTES;
        const int k0 = c * BKC;
#pragma unroll
        for (int i = 0; i < 2; i++) {
            int job = tid + i * 256;          // 512 jobs: 128 rows x 4 segs
            int r = job >> 2;
            int seg = job & 3;
            size_t goff = (size_t)r * K + k0 + seg * 8;
            uint32_t soff = (uint32_t)r * (BKP * 2) + seg * 16;
            cp_async16(st + soff,                 Ahb + goff);
            cp_async16(st + ARR_BYTES + soff,     Alb + goff);
            cp_async16(st + 2 * ARR_BYTES + soff, Bhb + goff);
            cp_async16(st + 3 * ARR_BYTES + soff, Blb + goff);
        }
    };

    wmma::fragment<wmma::accumulator, 16, 16, 16, float> acc[2][4];
#pragma unroll
    for (int i = 0; i < 2; i++)
#pragma unroll
        for (int j = 0; j < 4; j++) wmma::fill_fragment(acc[i][j], 0.0f);

#pragma unroll
    for (int s = 0; s < NSTAGE; s++) { load_stage(s, s); cp_commit(); }

    const int wm = (wid & 3) * 32;
    const int wn = (wid >> 2) * 64;

    for (int c = 0; c < nK; c++) {
        cp_wait_group<NSTAGE - 1>();
        __syncthreads();

        const char* st = smem + (c % NSTAGE) * STAGE_BYTES;
        const __nv_bfloat16* As_h = (const __nv_bfloat16*)st;
        const __nv_bfloat16* As_l = As_h + 128 * BKP;
        const __nv_bfloat16* Bs_h = As_h + 2 * 128 * BKP;
        const __nv_bfloat16* Bs_l = As_h + 3 * 128 * BKP;

#pragma unroll
        for (int ks = 0; ks < 2; ks++) {
            wmma::fragment<wmma::matrix_a, 16, 16, 16, __nv_bfloat16, wmma::row_major> fah[2], fal[2];
            wmma::fragment<wmma::matrix_b, 16, 16, 16, __nv_bfloat16, wmma::col_major> fbh[4], fbl[4];
#pragma unroll
            for (int i = 0; i < 2; i++) {
                wmma::load_matrix_sync(fah[i], As_h + (wm + i * 16) * BKP + ks * 16, BKP);
                wmma::load_matrix_sync(fal[i], As_l + (wm + i * 16) * BKP + ks * 16, BKP);
            }
#pragma unroll
            for (int j = 0; j < 4; j++) {
                wmma::load_matrix_sync(fbh[j], Bs_h + (wn + j * 16) * BKP + ks * 16, BKP);
                wmma::load_matrix_sync(fbl[j], Bs_l + (wn + j * 16) * BKP + ks * 16, BKP);
            }
#pragma unroll
            for (int i = 0; i < 2; i++)
#pragma unroll
                for (int j = 0; j < 4; j++) {
                    wmma::mma_sync(acc[i][j], fah[i], fbh[j], acc[i][j]);
                    wmma::mma_sync(acc[i][j], fah[i], fbl[j], acc[i][j]);
                    wmma::mma_sync(acc[i][j], fal[i], fbh[j], acc[i][j]);
                }
        }
        __syncthreads();
        if (c + NSTAGE < nK) load_stage(c % NSTAGE, c + NSTAGE);
        cp_commit();
    }
    cp_wait_group<0>();
    __syncthreads();

    // epilogue via smem staging
    float* Cs = (float*)smem;
#pragma unroll
    for (int i = 0; i < 2; i++)
#pragma unroll
        for (int j = 0; j < 4; j++)
            wmma::store_matrix_sync(Cs + (wm + i * 16) * 128 + wn + j * 16,
                                    acc[i][j], 128, wmma::mem_row_major);
    __syncthreads();

#pragma unroll
    for (int it = 0; it < 16; it++) {
        int g = tid + it * 256;               // 4096 float4 groups
        int r = g >> 5, c4 = (g & 31) * 4;
        float4 v = *reinterpret_cast<const float4*>(Cs + r * 128 + c4);
        float o0 = v.x * alpha, o1 = v.y * alpha;
        float o2 = v.z * alpha, o3 = v.w * alpha;
        if (bias) {
            o0 += bias[n0 + c4 + 0];
            o1 += bias[n0 + c4 + 1];
            o2 += bias[n0 + c4 + 2];
            o3 += bias[n0 + c4 + 3];
        }
        if (outF) {
            float4 w = {o0, o1, o2, o3};
            *reinterpret_cast<float4*>(outF + (size_t)bz * cStride
                + (size_t)(m0 + r) * ldC + n0 + c4) = w;
        }
        if (outH) {
            uint2 H, L;
            split2(o0, o1, H.x, L.x);
            split2(o2, o3, H.y, L.y);
            size_t e = (size_t)bz * pStride + (size_t)(m0 + r) * ldP + n0 + c4;
            *reinterpret_cast<uint2*>((char*)outH + e * 2) = H;
            *reinterpret_cast<uint2*>((char*)outL + e * 2) = L;
        }
    }
}

// ---------------------------------------------------------------------------
extern "C" void kernel_launch(void* const* d_in, const int* in_sizes, int n_in,
                              void* d_out, int out_size)
{
    const float* query = (const float*)d_in[0];
    const float* key   = (const float*)d_in[1];
    const float* value = (const float*)d_in[2];
    const float* Wq    = (const float*)d_in[3];
    const float* bq    = (const float*)d_in[4];
    const float* Wk    = (const float*)d_in[5];
    const float* bk    = (const float*)d_in[6];
    const float* Wv    = (const float*)d_in[7];
    const float* bv    = (const float*)d_in[8];
    float* out = (float*)d_out;

    cudaFuncSetAttribute(tc_gemm, cudaFuncAttributeMaxDynamicSharedMemorySize,
                         GEMM_SMEM);

    __nv_bfloat16 *xqh, *xql, *xkh, *xkl, *xvh, *xvl;
    __nv_bfloat16 *wqh, *wql, *wkh, *wkl, *wvh, *wvl;
    __nv_bfloat16 *Qh, *Ql, *Kh, *Kl, *Vth, *Vtl, *Sh, *Sl;
    float *Vf, *Sf;
    cudaGetSymbolAddress((void**)&xqh, g_xqh); cudaGetSymbolAddress((void**)&xql, g_xql);
    cudaGetSymbolAddress((void**)&xkh, g_xkh); cudaGetSymbolAddress((void**)&xkl, g_xkl);
    cudaGetSymbolAddress((void**)&xvh, g_xvh); cudaGetSymbolAddress((void**)&xvl, g_xvl);
    cudaGetSymbolAddress((void**)&wqh, g_wqh); cudaGetSymbolAddress((void**)&wql, g_wql);
    cudaGetSymbolAddress((void**)&wkh, g_wkh); cudaGetSymbolAddress((void**)&wkl, g_wkl);
    cudaGetSymbolAddress((void**)&wvh, g_wvh); cudaGetSymbolAddress((void**)&wvl, g_wvl);
    cudaGetSymbolAddress((void**)&Qh, g_Qh);   cudaGetSymbolAddress((void**)&Ql, g_Ql);
    cudaGetSymbolAddress((void**)&Kh, g_Kh);   cudaGetSymbolAddress((void**)&Kl, g_Kl);
    cudaGetSymbolAddress((void**)&Vf, g_Vf);
    cudaGetSymbolAddress((void**)&Vth, g_Vth); cudaGetSymbolAddress((void**)&Vtl, g_Vtl);
    cudaGetSymbolAddress((void**)&Sf, g_Sf);
    cudaGetSymbolAddress((void**)&Sh, g_Sh);   cudaGetSymbolAddress((void**)&Sl, g_Sl);

    // 1) pack inputs and weights (row-major hi/lo)
    convert_pack<<<4096, 256>>>(query, xqh, xql);
    convert_pack<<<4096, 256>>>(key,   xkh, xkl);
    convert_pack<<<4096, 256>>>(value, xvh, xvl);
    convert_pack<<<512, 256>>>(Wq, wqh, wql);
    convert_pack<<<512, 256>>>(Wk, wkh, wkl);
    convert_pack<<<512, 256>>>(Wv, wvh, wvl);

    // 2) projections: [8192,1024] x W^T + b
    dim3 gp(8, 64, 1);
    tc_gemm<<<gp, 256, GEMM_SMEM>>>(xqh, xql, wqh, wql, CH, 0, 0, bq, 1.0f,
                                    nullptr, 0, 0, Qh, Ql, CH, 0);
    tc_gemm<<<gp, 256, GEMM_SMEM>>>(xkh, xkl, wkh, wkl, CH, 0, 0, bk, 1.0f,
                                    nullptr, 0, 0, Kh, Kl, CH, 0);
    tc_gemm<<<gp, 256, GEMM_SMEM>>>(xvh, xvl, wvh, wvl, CH, 0, 0, bv, 1.0f,
                                    Vf, CH, 0, nullptr, nullptr, 0, 0);

    // 3) V -> V^T hi/lo
    transpose_pack<<<dim3(32, 8, 4), 256>>>(Vf, Vth, Vtl);

    // 4) scores: per batch [2048,1024] x [2048,1024]^T / 32
    dim3 gs(16, 16, 4);
    tc_gemm<<<gs, 256, GEMM_SMEM>>>(Qh, Ql, Kh, Kl, CH,
                                    (size_t)SEQ * CH, (size_t)SEQ * CH,
                                    nullptr, 1.0f / 32.0f,
                                    Sf, SEQ, (size_t)SEQ * SEQ,
                                    nullptr, nullptr, 0, 0);

    // 5) softmax + repack attn
    softmax_pack<<<BATCH * SEQ, 256>>>(Sf, Sh, Sl);

    // 6) out = attn @ V: per batch [2048,2048] x Vt[1024,2048]^T
    dim3 go(8, 16, 4);
    tc_gemm<<<go, 256, GEMM_SMEM>>>(Sh, Sl, Vth, Vtl, SEQ,
                                    (size_t)SEQ * SEQ, (size_t)CH * SEQ,
                                    nullptr, 1.0f,
                                    out, CH, (size_t)SEQ * CH,
                                    nullptr, nullptr, 0, 0);
}